// round 3
// baseline (speedup 1.0000x reference)
#include <cuda_runtime.h>
#include <cuda_fp16.h>
#include <mma.h>
#include <cstddef>

using namespace nvcuda;

// Problem dims
#define BB     16
#define HH     64
#define WWIDTH 64
#define HW     4096          // 64*64
#define IN_CH  1024
#define OUT_CH 768
#define ATT    256

// ---------------- scratch (device globals; no allocation) ----------------
__device__ __half g_t[(size_t)BB * IN_CH * HW];            // depthwise output, fp16, [b][ic][h][w]
__device__ __half g_fm[(size_t)BB * HH * OUT_CH * WWIDTH]; // pointwise output, fp16, [b][h][oc][w]
__device__ __half g_w[OUT_CH * IN_CH];                     // pw weights fp16, [oc][ic]

// ---------------- K0: convert pointwise weights to fp16 ----------------
__global__ void convert_w_kernel(const float* __restrict__ pw_w) {
    int oc = blockIdx.x;
    for (int i = threadIdx.x; i < IN_CH; i += blockDim.x)
        g_w[oc * IN_CH + i] = __float2half(pw_w[oc * IN_CH + i]);
}

// ---------------- K1: fused concat + depthwise 3x3 + bias -> fp16 ----------------
__global__ void dw_kernel(const float* __restrict__ x, const float* __restrict__ y,
                          const float* __restrict__ dw_w, const float* __restrict__ dw_b) {
    __shared__ float tile[66][68];
    int plane = blockIdx.x;                 // b*1024 + ic
    int b = plane >> 10, ic = plane & 1023;
    const float* src = (ic < 512) ? (x + ((size_t)b * 512 + ic) * HW)
                                  : (y + ((size_t)b * 512 + (ic - 512)) * HW);
    float w[9];
#pragma unroll
    for (int j = 0; j < 9; j++) w[j] = dw_w[ic * 9 + j];
    float bias = dw_b[ic];

    for (int i = threadIdx.x; i < 66 * 66; i += blockDim.x) {
        int r = i / 66, c = i - r * 66;
        int gh = r - 1, gw = c - 1;
        float v = 0.f;
        if (gh >= 0 && gh < 64 && gw >= 0 && gw < 64) v = src[gh * 64 + gw];
        tile[r][c] = v;
    }
    __syncthreads();

    __half* dst = g_t + (size_t)plane * HW;
    for (int p = threadIdx.x; p < HW; p += blockDim.x) {
        int h = p >> 6, ww = p & 63;
        float acc = bias;
#pragma unroll
        for (int kh = 0; kh < 3; kh++)
#pragma unroll
            for (int kw = 0; kw < 3; kw++)
                acc += tile[h + kh][ww + kw] * w[kh * 3 + kw];
        dst[p] = __float2half(acc);
    }
}

// ---------------- K2: pointwise GEMM (fp16 HMMA, fp32 accum) + bias -> fp16 fm ----------------
// Tile: M=128 (oc) x N=256 (pixels of one batch image) x K=64 per chunk; 8 warps, each 64x64.
// Output layout: g_fm[b][h][oc][w] so attention reads contiguous 768x64 slabs per (b,h).
#define PW_AS_BYTES (128 * 72 * 2)   // 18432
#define PW_BS_BYTES (64 * 264 * 2)   // 33792
#define PW_EPI_BYTES (8 * 16 * 72 * 4) // 36864
#define PW_SMEM (PW_AS_BYTES + PW_BS_BYTES + PW_EPI_BYTES)  // 89088

__global__ void __launch_bounds__(256) pw_kernel(const float* __restrict__ pw_b) {
    extern __shared__ char smem[];
    __half* As = (__half*)smem;                             // [128][72] (k padded)
    __half* Bs = (__half*)(smem + PW_AS_BYTES);             // [64][264]
    float*  Epi = (float*)(smem + PW_AS_BYTES + PW_BS_BYTES); // 8 x [16][72]

    int oc0 = blockIdx.x * 128;
    int p0  = blockIdx.y * 256;
    int b   = blockIdx.z;
    int tid = threadIdx.x;
    int warp = tid >> 5, lane = tid & 31;
    int warp_m = warp >> 2, warp_n = warp & 3;   // 2 x 4 warp grid

    wmma::fragment<wmma::accumulator, 16, 16, 16, float> acc[4][4];
#pragma unroll
    for (int i = 0; i < 4; i++)
#pragma unroll
        for (int j = 0; j < 4; j++) wmma::fill_fragment(acc[i][j], 0.f);

    const __half* tbase = g_t + (size_t)b * IN_CH * HW + p0;

    for (int kc = 0; kc < IN_CH; kc += 64) {
        // A: 128 x 64 halves from g_w  (1024 float4 loads)
#pragma unroll
        for (int it = 0; it < 4; it++) {
            int i = tid + it * 256;
            int row = i >> 3, seg = i & 7;
            *(float4*)(As + row * 72 + seg * 8) =
                *(const float4*)(g_w + (oc0 + row) * IN_CH + kc + seg * 8);
        }
        // B: 64 x 256 halves from g_t  (2048 float4 loads)
#pragma unroll
        for (int it = 0; it < 8; it++) {
            int i = tid + it * 256;
            int row = i >> 5, seg = i & 31;
            *(float4*)(Bs + row * 264 + seg * 8) =
                *(const float4*)(tbase + (size_t)(kc + row) * HW + seg * 8);
        }
        __syncthreads();
#pragma unroll
        for (int ks = 0; ks < 4; ks++) {
            int k = ks * 16;
            wmma::fragment<wmma::matrix_a, 16, 16, 16, __half, wmma::row_major> a[4];
            wmma::fragment<wmma::matrix_b, 16, 16, 16, __half, wmma::row_major> bf[4];
#pragma unroll
            for (int i = 0; i < 4; i++)
                wmma::load_matrix_sync(a[i], As + (warp_m * 64 + i * 16) * 72 + k, 72);
#pragma unroll
            for (int j = 0; j < 4; j++)
                wmma::load_matrix_sync(bf[j], Bs + k * 264 + warp_n * 64 + j * 16, 264);
#pragma unroll
            for (int i = 0; i < 4; i++)
#pragma unroll
                for (int j = 0; j < 4; j++)
                    wmma::mma_sync(acc[i][j], a[i], bf[j], acc[i][j]);
        }
        __syncthreads();
    }

    // Epilogue: stage per-warp through smem, add bias (fp32), convert fp16,
    // scatter to g_fm[b][h][oc][w].  (p0+n0) is 64-aligned so h is fixed per warp.
    float* scratch = Epi + warp * 16 * 72;
    int m0 = warp_m * 64, n0 = warp_n * 64;
    int h = (p0 + n0) >> 6;
#pragma unroll
    for (int fm = 0; fm < 4; fm++) {
#pragma unroll
        for (int fn = 0; fn < 4; fn++)
            wmma::store_matrix_sync(scratch + fn * 16, acc[fm][fn], 72, wmma::mem_row_major);
        __syncwarp();
        int ocr = oc0 + m0 + fm * 16;
        for (int i = lane; i < 16 * 64; i += 32) {
            int r = i >> 6, c = i & 63;
            float v = scratch[r * 72 + c] + pw_b[ocr + r];
            g_fm[((size_t)(b * 64 + h) * 768 + ocr + r) * 64 + c] = __float2half(v);
        }
        __syncwarp();
    }
}

// ---------------- K3: attention per (b,h): dots=QK^T, softmax, out=PV ----------------
// smem: Q,K,V fp16 [256][72]; S fp32 [64][264]; P fp16 [64][264]
#define ATT_Q_OFF  0
#define ATT_K_OFF  (256 * 72 * 2)
#define ATT_V_OFF  (2 * 256 * 72 * 2)
#define ATT_S_OFF  (3 * 256 * 72 * 2)            // 110592
#define ATT_P_OFF  (ATT_S_OFF + 64 * 264 * 4)    // 178176
#define ATT_SMEM   (ATT_P_OFF + 64 * 264 * 2)    // 211968

__global__ void __launch_bounds__(256) attn_kernel(float* __restrict__ out) {
    extern __shared__ char smem[];
    __half* Qs = (__half*)(smem + ATT_Q_OFF);
    __half* Ks = (__half*)(smem + ATT_K_OFF);
    __half* Vs = (__half*)(smem + ATT_V_OFF);
    float*  Ss = (float*)(smem + ATT_S_OFF);
    __half* Ps = (__half*)(smem + ATT_P_OFF);

    int bh = blockIdx.x;
    int tid = threadIdx.x;
    int warp = tid >> 5;

    // Load Q,K,V (768 x 64 fp16, contiguous per (b,h)) into padded smem
    const __half* src = g_fm + (size_t)bh * 768 * 64;
    for (int i = tid; i < 768 * 8; i += 256) {
        int row = i >> 3, seg = i & 7;
        float4 v = *(const float4*)(src + row * 64 + seg * 8);
        __half* d;
        if (row < 256)      d = Qs + row * 72 + seg * 8;
        else if (row < 512) d = Ks + (row - 256) * 72 + seg * 8;
        else                d = Vs + (row - 512) * 72 + seg * 8;
        *(float4*)d = v;
    }
    __syncthreads();

    for (int mt = 0; mt < 4; mt++) {
        // ---- S[64][256] = Q_tile @ K^T : 8 warps as 2(M) x 4(N), warp tile 32x64
        {
            int wm = warp >> 2, wn = warp & 3;
            wmma::fragment<wmma::accumulator, 16, 16, 16, float> s[2][4];
#pragma unroll
            for (int i = 0; i < 2; i++)
#pragma unroll
                for (int j = 0; j < 4; j++) wmma::fill_fragment(s[i][j], 0.f);
#pragma unroll
            for (int k = 0; k < 64; k += 16) {
                wmma::fragment<wmma::matrix_a, 16, 16, 16, __half, wmma::row_major> a[2];
                wmma::fragment<wmma::matrix_b, 16, 16, 16, __half, wmma::col_major> bf[4];
#pragma unroll
                for (int i = 0; i < 2; i++)
                    wmma::load_matrix_sync(a[i], Qs + (mt * 64 + wm * 32 + i * 16) * 72 + k, 72);
#pragma unroll
                for (int j = 0; j < 4; j++)
                    wmma::load_matrix_sync(bf[j], Ks + (wn * 64 + j * 16) * 72 + k, 72);
#pragma unroll
                for (int i = 0; i < 2; i++)
#pragma unroll
                    for (int j = 0; j < 4; j++)
                        wmma::mma_sync(s[i][j], a[i], bf[j], s[i][j]);
            }
#pragma unroll
            for (int i = 0; i < 2; i++)
#pragma unroll
                for (int j = 0; j < 4; j++)
                    wmma::store_matrix_sync(Ss + (wm * 32 + i * 16) * 264 + wn * 64 + j * 16,
                                            s[i][j], 264, wmma::mem_row_major);
        }
        __syncthreads();

        // ---- softmax over 256 cols; 4 threads per row
        {
            int r = tid >> 2, l4 = tid & 3;
            float* row = Ss + r * 264;
            float mx = -1e30f;
#pragma unroll 8
            for (int j = 0; j < 64; j++) mx = fmaxf(mx, row[l4 + j * 4]);
            mx = fmaxf(mx, __shfl_xor_sync(0xffffffffu, mx, 1));
            mx = fmaxf(mx, __shfl_xor_sync(0xffffffffu, mx, 2));
            float sum = 0.f;
#pragma unroll 8
            for (int j = 0; j < 64; j++) {
                int c = l4 + j * 4;
                float e = __expf(row[c] - mx);
                row[c] = e;
                sum += e;
            }
            sum += __shfl_xor_sync(0xffffffffu, sum, 1);
            sum += __shfl_xor_sync(0xffffffffu, sum, 2);
            float inv = 1.f / sum;
            __half* prow = Ps + r * 264;
#pragma unroll 8
            for (int j = 0; j < 64; j++) {
                int c = l4 + j * 4;
                prow[c] = __float2half(row[c] * inv);
            }
        }
        __syncthreads();

        // ---- O[64][64] = P @ V : 8 warps as 4(M) x 2(N), warp tile 16x32; direct global store
        {
            int wm = warp >> 1, wn = warp & 1;
            wmma::fragment<wmma::accumulator, 16, 16, 16, float> o[2];
            wmma::fill_fragment(o[0], 0.f);
            wmma::fill_fragment(o[1], 0.f);
#pragma unroll
            for (int k = 0; k < 256; k += 16) {
                wmma::fragment<wmma::matrix_a, 16, 16, 16, __half, wmma::row_major> a;
                wmma::fragment<wmma::matrix_b, 16, 16, 16, __half, wmma::row_major> bf[2];
                wmma::load_matrix_sync(a, Ps + (wm * 16) * 264 + k, 264);
#pragma unroll
                for (int j = 0; j < 2; j++)
                    wmma::load_matrix_sync(bf[j], Vs + k * 72 + wn * 32 + j * 16, 72);
                wmma::mma_sync(o[0], a, bf[0], o[0]);
                wmma::mma_sync(o[1], a, bf[1], o[1]);
            }
            // out[b,h,att,w] is exactly row-major d_out: ((bh*256 + att)*64 + w)
            float* dst = out + ((size_t)bh * 256 + mt * 64 + wm * 16) * 64 + wn * 32;
            wmma::store_matrix_sync(dst,      o[0], 64, wmma::mem_row_major);
            wmma::store_matrix_sync(dst + 16, o[1], 64, wmma::mem_row_major);
        }
        __syncthreads();
    }
}

// ---------------- launch ----------------
extern "C" void kernel_launch(void* const* d_in, const int* in_sizes, int n_in,
                              void* d_out, int out_size) {
    const float* x    = (const float*)d_in[0];
    const float* y    = (const float*)d_in[1];
    const float* dw_w = (const float*)d_in[2];
    const float* dw_b = (const float*)d_in[3];
    const float* pw_w = (const float*)d_in[4];
    const float* pw_b = (const float*)d_in[5];
    float* out = (float*)d_out;

    cudaFuncSetAttribute(pw_kernel,  cudaFuncAttributeMaxDynamicSharedMemorySize, PW_SMEM);
    cudaFuncSetAttribute(attn_kernel, cudaFuncAttributeMaxDynamicSharedMemorySize, ATT_SMEM);

    convert_w_kernel<<<OUT_CH, 256>>>(pw_w);
    dw_kernel<<<BB * IN_CH, 256>>>(x, y, dw_w, dw_b);
    pw_kernel<<<dim3(6, 16, 16), 256, PW_SMEM>>>(pw_b);
    attn_kernel<<<BB * HH, 256, ATT_SMEM>>>(out);
}

// round 5
// speedup vs baseline: 1.2183x; 1.2183x over previous
#include <cuda_runtime.h>
#include <cuda_fp16.h>
#include <mma.h>
#include <cstddef>
#include <cstdint>

using namespace nvcuda;

// Problem dims
#define BB     16
#define HH     64
#define HW     4096
#define IN_CH  1024
#define OUT_CH 768
#define ATT    256

// ---------------- scratch (device globals; no allocation) ----------------
__device__ __half g_t[(size_t)BB * IN_CH * HW];            // depthwise out fp16 [b][ic][h][w]
__device__ __half g_fm[(size_t)BB * HH * OUT_CH * 64];     // pointwise out fp16 [b][h][oc][w]
__device__ __half g_w[OUT_CH * IN_CH];                     // pw weights fp16 [oc][ic]

// ---------------- PTX helpers ----------------
__device__ __forceinline__ uint32_t smem_u32(const void* p) {
    return (uint32_t)__cvta_generic_to_shared(p);
}
__device__ __forceinline__ void ldsm_x4(uint32_t* r, uint32_t addr) {
    asm volatile("ldmatrix.sync.aligned.m8n8.x4.shared.b16 {%0,%1,%2,%3}, [%4];\n"
        : "=r"(r[0]), "=r"(r[1]), "=r"(r[2]), "=r"(r[3]) : "r"(addr));
}
__device__ __forceinline__ void ldsm_x4_t(uint32_t* r, uint32_t addr) {
    asm volatile("ldmatrix.sync.aligned.m8n8.x4.trans.shared.b16 {%0,%1,%2,%3}, [%4];\n"
        : "=r"(r[0]), "=r"(r[1]), "=r"(r[2]), "=r"(r[3]) : "r"(addr));
}
__device__ __forceinline__ void mma_16816(float* c, const uint32_t* a, const uint32_t* b) {
    asm volatile(
        "mma.sync.aligned.m16n8k16.row.col.f32.f16.f16.f32 "
        "{%0,%1,%2,%3}, {%4,%5,%6,%7}, {%8,%9}, {%0,%1,%2,%3};\n"
        : "+f"(c[0]), "+f"(c[1]), "+f"(c[2]), "+f"(c[3])
        : "r"(a[0]), "r"(a[1]), "r"(a[2]), "r"(a[3]), "r"(b[0]), "r"(b[1]));
}
__device__ __forceinline__ void cp_async16(void* dst, const void* src) {
    asm volatile("cp.async.cg.shared.global [%0], [%1], 16;\n"
        :: "r"(smem_u32(dst)), "l"(src));
}
#define CP_COMMIT() asm volatile("cp.async.commit_group;\n")
#define CP_WAIT(n)  asm volatile("cp.async.wait_group %0;\n" :: "n"(n))

__device__ __forceinline__ uint32_t pack2(float x, float y) {
    __half2 h = __floats2half2_rn(x, y);
    return *(uint32_t*)&h;
}

// ---------------- K0: convert pointwise weights to fp16 ----------------
__global__ void convert_w_kernel(const float* __restrict__ pw_w) {
    int oc = blockIdx.x;
    for (int i = threadIdx.x; i < IN_CH; i += blockDim.x)
        g_w[oc * IN_CH + i] = __float2half(pw_w[oc * IN_CH + i]);
}

// ---------------- K1: fused concat + depthwise 3x3 + bias -> fp16 ----------------
__global__ void dw_kernel(const float* __restrict__ x, const float* __restrict__ y,
                          const float* __restrict__ dw_w, const float* __restrict__ dw_b) {
    __shared__ float tile[66][68];
    int plane = blockIdx.x;                 // b*1024 + ic
    int b = plane >> 10, ic = plane & 1023;
    const float* src = (ic < 512) ? (x + ((size_t)b * 512 + ic) * HW)
                                  : (y + ((size_t)b * 512 + (ic - 512)) * HW);
    float w[9];
#pragma unroll
    for (int j = 0; j < 9; j++) w[j] = dw_w[ic * 9 + j];
    float bias = dw_b[ic];

    for (int i = threadIdx.x; i < 66 * 66; i += blockDim.x) {
        int r = i / 66, c = i - r * 66;
        int gh = r - 1, gw = c - 1;
        float v = 0.f;
        if (gh >= 0 && gh < 64 && gw >= 0 && gw < 64) v = src[gh * 64 + gw];
        tile[r][c] = v;
    }
    __syncthreads();

    __half* dst = g_t + (size_t)plane * HW;
    for (int p = threadIdx.x * 2; p < HW; p += blockDim.x * 2) {
        int h = p >> 6, ww = p & 63;
        float a0 = bias, a1 = bias;
#pragma unroll
        for (int kh = 0; kh < 3; kh++)
#pragma unroll
            for (int kw = 0; kw < 3; kw++) {
                float wv = w[kh * 3 + kw];
                a0 += tile[h + kh][ww + kw] * wv;
                a1 += tile[h + kh][ww + 1 + kw] * wv;
            }
        *(__half2*)(dst + p) = __floats2half2_rn(a0, a1);
    }
}

// ---------------- K2: pointwise GEMM, M=256 N=128 K=32, 3-stage cp.async ----------------
#define PW_A_ST (256 * 40)                 // halves per A stage (k padded 32->40)
#define PW_B_ST (32 * 136)                 // halves per B stage (n padded 128->136)
#define PW_STAGE (PW_A_ST + PW_B_ST)       // 14592 halves
#define PW_SMEM  (3 * PW_STAGE * 2)        // 87552 bytes

__device__ __forceinline__ void pw_load_stage(__half* A, __half* B, int tid,
                                              const __half* wbase, const __half* tbase, int kc) {
#pragma unroll
    for (int t = 0; t < 4; t++) {               // A: 256x32 halves
        int i = tid + t * 256;
        int row = i >> 2, seg = i & 3;
        cp_async16(A + row * 40 + seg * 8, wbase + (size_t)row * IN_CH + kc + seg * 8);
    }
#pragma unroll
    for (int t = 0; t < 2; t++) {               // B: 32x128 halves
        int i = tid + t * 256;
        int row = i >> 4, seg = i & 15;
        cp_async16(B + row * 136 + seg * 8, tbase + (size_t)(kc + row) * HW + seg * 8);
    }
}

__global__ void __launch_bounds__(256, 1) pw_kernel(const float* __restrict__ pw_b) {
    extern __shared__ __half sh[];
    int oc0 = blockIdx.x * 256;
    int p0  = blockIdx.y * 128;
    int b   = blockIdx.z;
    int tid = threadIdx.x;
    int warp = tid >> 5, lane = tid & 31;
    int wm = warp >> 1, wn = warp & 1;          // 4(M) x 2(N) warps, warp tile 64x64

    wmma::fragment<wmma::accumulator, 16, 16, 16, float> acc[4][4];
#pragma unroll
    for (int i = 0; i < 4; i++)
#pragma unroll
        for (int j = 0; j < 4; j++) wmma::fill_fragment(acc[i][j], 0.f);

    const __half* wbase = g_w + (size_t)oc0 * IN_CH;
    const __half* tbase = g_t + (size_t)b * IN_CH * HW + p0;

    pw_load_stage(sh, sh + PW_A_ST, tid, wbase, tbase, 0);  CP_COMMIT();
    pw_load_stage(sh + PW_STAGE, sh + PW_STAGE + PW_A_ST, tid, wbase, tbase, 32); CP_COMMIT();

    for (int kt = 0; kt < 32; kt++) {
        CP_WAIT(1);
        __syncthreads();
        int knext = kt + 2;
        if (knext < 32) {
            __half* An = sh + (knext % 3) * PW_STAGE;
            pw_load_stage(An, An + PW_A_ST, tid, wbase, tbase, knext * 32);
        }
        CP_COMMIT();

        __half* A = sh + (kt % 3) * PW_STAGE;
        __half* B = A + PW_A_ST;
#pragma unroll
        for (int ks = 0; ks < 2; ks++) {
            wmma::fragment<wmma::matrix_a, 16, 16, 16, __half, wmma::row_major> af[4];
            wmma::fragment<wmma::matrix_b, 16, 16, 16, __half, wmma::row_major> bf[4];
#pragma unroll
            for (int i = 0; i < 4; i++)
                wmma::load_matrix_sync(af[i], A + (wm * 64 + i * 16) * 40 + ks * 16, 40);
#pragma unroll
            for (int j = 0; j < 4; j++)
                wmma::load_matrix_sync(bf[j], B + ks * 16 * 136 + wn * 64 + j * 16, 136);
#pragma unroll
            for (int i = 0; i < 4; i++)
#pragma unroll
                for (int j = 0; j < 4; j++)
                    wmma::mma_sync(acc[i][j], af[i], bf[j], acc[i][j]);
        }
    }
    __syncthreads();

    // epilogue: stage through smem (reuse stage buffers), bias, fp16 -> g_fm[b][h][oc][w]
    float* scratch = (float*)sh + warp * 16 * 72;
    int h = blockIdx.y * 2 + wn;                // p0 + wn*64 is 64-aligned
    size_t fmbase = ((size_t)(b * 64 + h) * OUT_CH) * 64;
#pragma unroll
    for (int fmt = 0; fmt < 4; fmt++) {
#pragma unroll
        for (int fn = 0; fn < 4; fn++)
            wmma::store_matrix_sync(scratch + fn * 16, acc[fmt][fn], 72, wmma::mem_row_major);
        __syncwarp();
        int ocr = oc0 + wm * 64 + fmt * 16;
        for (int i = lane; i < 16 * 32; i += 32) {
            int r = i >> 5, c2 = (i & 31) * 2;
            float v0 = scratch[r * 72 + c2] + pw_b[ocr + r];
            float v1 = scratch[r * 72 + c2 + 1] + pw_b[ocr + r];
            *(__half2*)(g_fm + fmbase + (size_t)(ocr + r) * 64 + c2) = __floats2half2_rn(v0, v1);
        }
        __syncwarp();
    }
}

// ---------------- K3: attention, register-resident S/P via mma.m16n8k16 ----------------
// smem: Q,K,V fp16 [256][72] = 110592 B.  Block = (b,h), 8 warps, warp = 16 rows x 2 passes.
#define ATT_SMEM (3 * 256 * 72 * 2)

__global__ void __launch_bounds__(256, 1) attn_kernel(float* __restrict__ out) {
    extern __shared__ __half sm[];
    __half* Qs = sm;
    __half* Ks = sm + 256 * 72;
    __half* Vs = sm + 2 * 256 * 72;

    int bh = blockIdx.x;
    int tid = threadIdx.x;
    int warp = tid >> 5, lane = tid & 31;

    // load QKV (768 x 64 fp16 contiguous per bh)
    const __half* src = g_fm + (size_t)bh * OUT_CH * 64;
    for (int i = tid; i < 768 * 8; i += 256) {
        int row = i >> 3, seg = i & 7;
        float4 v = *(const float4*)(src + row * 64 + seg * 8);
        __half* d = (row < 256) ? Qs + row * 72 + seg * 8
                  : (row < 512) ? Ks + (row - 256) * 72 + seg * 8
                                : Vs + (row - 512) * 72 + seg * 8;
        *(float4*)d = v;
    }
    __syncthreads();

    uint32_t qb = smem_u32(Qs), kb = smem_u32(Ks), vb = smem_u32(Vs);
    int lrow = lane & 15;                 // ldmatrix row within 16
    int lcol = (lane >> 4) << 3;          // 0 or 8 halves

    for (int pass = 0; pass < 2; pass++) {
        int m0 = pass * 128 + warp * 16;

        // ---- S[16][256] = Q_tile @ K^T, in registers ----
        float s[32][4];
#pragma unroll
        for (int j = 0; j < 32; j++) { s[j][0] = s[j][1] = s[j][2] = s[j][3] = 0.f; }
#pragma unroll
        for (int k = 0; k < 64; k += 16) {
            uint32_t a[4];
            ldsm_x4(a, qb + (uint32_t)((m0 + lrow) * 72 + k + lcol) * 2);
#pragma unroll
            for (int nb = 0; nb < 16; nb++) {
                uint32_t t[4];
                ldsm_x4(t, kb + (uint32_t)((nb * 16 + lrow) * 72 + k + lcol) * 2);
                uint32_t b0[2] = { t[0], t[2] };
                uint32_t b1[2] = { t[1], t[3] };
                mma_16816(s[2 * nb],     a, b0);
                mma_16816(s[2 * nb + 1], a, b1);
            }
        }

        // ---- softmax over 256 cols, in registers ----
        // thread owns: row r = m0 + lane/4 (c0,c1) and row r+8 (c2,c3)
        float mx0 = -1e30f, mx1 = -1e30f;
#pragma unroll
        for (int j = 0; j < 32; j++) {
            mx0 = fmaxf(mx0, fmaxf(s[j][0], s[j][1]));
            mx1 = fmaxf(mx1, fmaxf(s[j][2], s[j][3]));
        }
        mx0 = fmaxf(mx0, __shfl_xor_sync(0xffffffffu, mx0, 1));
        mx0 = fmaxf(mx0, __shfl_xor_sync(0xffffffffu, mx0, 2));
        mx1 = fmaxf(mx1, __shfl_xor_sync(0xffffffffu, mx1, 1));
        mx1 = fmaxf(mx1, __shfl_xor_sync(0xffffffffu, mx1, 2));
        float sum0 = 0.f, sum1 = 0.f;
#pragma unroll
        for (int j = 0; j < 32; j++) {
            s[j][0] = __expf(s[j][0] - mx0); sum0 += s[j][0];
            s[j][1] = __expf(s[j][1] - mx0); sum0 += s[j][1];
            s[j][2] = __expf(s[j][2] - mx1); sum1 += s[j][2];
            s[j][3] = __expf(s[j][3] - mx1); sum1 += s[j][3];
        }
        sum0 += __shfl_xor_sync(0xffffffffu, sum0, 1);
        sum0 += __shfl_xor_sync(0xffffffffu, sum0, 2);
        sum1 += __shfl_xor_sync(0xffffffffu, sum1, 1);
        sum1 += __shfl_xor_sync(0xffffffffu, sum1, 2);
        float inv0 = 1.f / sum0, inv1 = 1.f / sum1;

        // ---- O[16][64] = P @ V ; P packed from S accumulators (C->A fragment identity) ----
        float o[8][4];
#pragma unroll
        for (int w8 = 0; w8 < 8; w8++) { o[w8][0] = o[w8][1] = o[w8][2] = o[w8][3] = 0.f; }
#pragma unroll
        for (int j = 0; j < 16; j++) {
            uint32_t a[4];
            a[0] = pack2(s[2 * j][0]     * inv0, s[2 * j][1]     * inv0);
            a[1] = pack2(s[2 * j][2]     * inv1, s[2 * j][3]     * inv1);
            a[2] = pack2(s[2 * j + 1][0] * inv0, s[2 * j + 1][1] * inv0);
            a[3] = pack2(s[2 * j + 1][2] * inv1, s[2 * j + 1][3] * inv1);
#pragma unroll
            for (int wq = 0; wq < 4; wq++) {
                uint32_t t[4];
                ldsm_x4_t(t, vb + (uint32_t)((j * 16 + lrow) * 72 + wq * 16 + lcol) * 2);
                uint32_t b0[2] = { t[0], t[1] };   // w-block wq*16
                uint32_t b1[2] = { t[2], t[3] };   // w-block wq*16 + 8
                mma_16816(o[2 * wq],     a, b0);
                mma_16816(o[2 * wq + 1], a, b1);
            }
        }

        // ---- store: out[((bh*256 + row)*64 + col] (row-major == reference reshape) ----
        int r0 = m0 + (lane >> 2);
        int c0 = (lane & 3) * 2;
        float* obase = out + ((size_t)bh * 256 + r0) * 64 + c0;
#pragma unroll
        for (int w8 = 0; w8 < 8; w8++) {
            *(float2*)(obase + w8 * 8)          = make_float2(o[w8][0], o[w8][1]);
            *(float2*)(obase + 8 * 64 + w8 * 8) = make_float2(o[w8][2], o[w8][3]);
        }
    }
}

// ---------------- launch ----------------
extern "C" void kernel_launch(void* const* d_in, const int* in_sizes, int n_in,
                              void* d_out, int out_size) {
    const float* x    = (const float*)d_in[0];
    const float* y    = (const float*)d_in[1];
    const float* dw_w = (const float*)d_in[2];
    const float* dw_b = (const float*)d_in[3];
    const float* pw_w = (const float*)d_in[4];
    const float* pw_b = (const float*)d_in[5];
    float* out = (float*)d_out;

    cudaFuncSetAttribute(pw_kernel,   cudaFuncAttributeMaxDynamicSharedMemorySize, PW_SMEM);
    cudaFuncSetAttribute(attn_kernel, cudaFuncAttributeMaxDynamicSharedMemorySize, ATT_SMEM);

    convert_w_kernel<<<OUT_CH, 256>>>(pw_w);
    dw_kernel<<<BB * IN_CH, 256>>>(x, y, dw_w, dw_b);
    pw_kernel<<<dim3(3, 32, 16), 256, PW_SMEM>>>(pw_b);
    attn_kernel<<<BB * HH, 256, ATT_SMEM>>>(out);
}